// round 1
// baseline (speedup 1.0000x reference)
#include <cuda_runtime.h>
#include <math.h>

// Problem constants
#define BB 256
#define N_SV 64
#define N_TRK 512
#define N_PFC 512
#define KNN 8
#define HH 32

// ---------------- scratch (static device arrays; no allocation) -------------
__device__ float g_sv [BB * N_SV  * HH];   // encoded SV
__device__ float g_trk[BB * N_TRK * HH];   // encoded TRK
__device__ float g_pfc[BB * N_PFC * HH];   // encoded PFC
__device__ float g_U  [BB * N_TRK * HH];   // dst-side linear (per conv)
__device__ float g_V  [BB * N_PFC * HH];   // src-side linear (per conv, max size)
__device__ float g_f1 [BB * N_TRK * HH];
__device__ float g_f2 [BB * N_TRK * HH];
__device__ float g_f3 [BB * N_TRK * HH];

__device__ __forceinline__ float eluf(float x) {
    return x > 0.f ? x : (expf(x) - 1.f);
}

// ---------------- encoder: 2-layer MLP, warp-per-node ----------------------
template <int FIN>
__global__ void encode_k(const float* __restrict__ x,
                         const float* __restrict__ W1, const float* __restrict__ b1,
                         const float* __restrict__ W2, const float* __restrict__ b2,
                         float* __restrict__ out, int n)
{
    __shared__ float w1s[FIN * 32];
    __shared__ float w2s[32 * 32];
    __shared__ float b1s[32], b2s[32];
    int tid = threadIdx.x;
    for (int i = tid; i < FIN * 32; i += 256) w1s[i] = W1[i];
    for (int i = tid; i < 1024;     i += 256) w2s[i] = W2[i];
    if (tid < 32) { b1s[tid] = b1[tid]; b2s[tid] = b2[tid]; }
    __syncthreads();

    int node = blockIdx.x * 8 + (tid >> 5);
    int lane = tid & 31;
    if (node >= n) return;

    float xv = (lane < FIN) ? x[node * FIN + lane] : 0.f;
    float h = b1s[lane];
#pragma unroll
    for (int i = 0; i < FIN; ++i)
        h = fmaf(__shfl_sync(0xffffffffu, xv, i), w1s[i * 32 + lane], h);
    h = eluf(h);

    float o = b2s[lane];
#pragma unroll
    for (int i = 0; i < 32; ++i)
        o = fmaf(__shfl_sync(0xffffffffu, h, i), w2s[i * 32 + lane], o);
    out[node * 32 + lane] = eluf(o);
}

// ---------------- 32x32 linear from conv_W (mode 0: (Wa-Wb)+b, mode 1: Wb) --
__global__ void lin32_k(const float* __restrict__ in,
                        const float* __restrict__ convW, const float* __restrict__ convB,
                        float* __restrict__ out, int n, int mode)
{
    __shared__ float ws[1024];
    __shared__ float bs[32];
    int tid = threadIdx.x;
    for (int i = tid; i < 1024; i += 256)
        ws[i] = (mode == 0) ? (convW[i] - convW[1024 + i]) : convW[1024 + i];
    if (tid < 32) bs[tid] = (mode == 0) ? convB[tid] : 0.f;
    __syncthreads();

    int node = blockIdx.x * 8 + (tid >> 5);
    int lane = tid & 31;
    if (node >= n) return;

    float xv = in[node * 32 + lane];
    float o = bs[lane];
#pragma unroll
    for (int i = 0; i < 32; ++i)
        o = fmaf(__shfl_sync(0xffffffffu, xv, i), ws[i * 32 + lane], o);
    out[node * 32 + lane] = o;
}

// ---------------- kNN + max aggregation -------------------------------------
// One block = (event e, dst tile of 256). Phase 1: stage src feats + ||xj||^2.
// Phase 2: thread-per-dst streaming top-8 (score = sq[s] - 2*xi.xj; xi holds
// -2*dst so the score accumulates with pure FMAs starting at sq[s]).
// Phase 3: warp-per-dst: out = elu(U + colmax_k V[idx]).
__global__ void knn_k(const float* __restrict__ src_enc,
                      const float* __restrict__ dst_enc,
                      const float* __restrict__ V,
                      const float* __restrict__ U,
                      float* __restrict__ out, int Ns)
{
    extern __shared__ float sm[];
    float* srcf = sm;                     // Ns*32
    float* sq   = sm + Ns * 32;           // Ns
    int*   idxs = (int*)(sq + Ns);        // 256*8

    int tid  = threadIdx.x;
    int lane = tid & 31;
    int wid  = tid >> 5;
    int e    = blockIdx.x >> 1;
    int tile = blockIdx.x & 1;

    const float* sbase = src_enc + (size_t)e * Ns * 32;
    for (int i = tid; i < Ns * 32; i += 256) srcf[i] = sbase[i];
    __syncthreads();

    // ||xj||^2 per src row, warp-cooperative (conflict-free)
    for (int r = wid; r < Ns; r += 8) {
        float v = srcf[r * 32 + lane];
        v *= v;
#pragma unroll
        for (int o = 16; o; o >>= 1) v += __shfl_down_sync(0xffffffffu, v, o);
        if (lane == 0) sq[r] = v;
    }
    __syncthreads();

    // phase 2: streaming top-8
    int dgn = e * 512 + tile * 256 + tid;   // global dst node
    float xi[32];
    {
        const float4* drow = reinterpret_cast<const float4*>(dst_enc + (size_t)dgn * 32);
#pragma unroll
        for (int q = 0; q < 8; ++q) {
            float4 v = drow[q];
            xi[4 * q + 0] = -2.f * v.x; xi[4 * q + 1] = -2.f * v.y;
            xi[4 * q + 2] = -2.f * v.z; xi[4 * q + 3] = -2.f * v.w;
        }
    }
    float dist[KNN];
    int   idx [KNN];
#pragma unroll
    for (int k = 0; k < KNN; ++k) { dist[k] = 3.4e38f; idx[k] = 0; }

    const float4* sf4 = reinterpret_cast<const float4*>(srcf);
    for (int s = 0; s < Ns; ++s) {
        const float4* srow = sf4 + s * 8;
        float d0 = sq[s], d1 = 0.f, d2 = 0.f, d3 = 0.f;
#pragma unroll
        for (int q = 0; q < 8; ++q) {
            float4 v = srow[q];
            d0 = fmaf(xi[4 * q + 0], v.x, d0);
            d1 = fmaf(xi[4 * q + 1], v.y, d1);
            d2 = fmaf(xi[4 * q + 2], v.z, d2);
            d3 = fmaf(xi[4 * q + 3], v.w, d3);
        }
        float sc = (d0 + d1) + (d2 + d3);
        if (sc < dist[KNN - 1]) {
            dist[KNN - 1] = sc; idx[KNN - 1] = s;
#pragma unroll
            for (int p = KNN - 1; p > 0; --p) {
                if (dist[p] < dist[p - 1]) {
                    float td = dist[p]; dist[p] = dist[p - 1]; dist[p - 1] = td;
                    int   ti = idx[p];  idx[p]  = idx[p - 1];  idx[p - 1]  = ti;
                }
            }
        }
    }
#pragma unroll
    for (int k = 0; k < KNN; ++k) idxs[tid * KNN + k] = idx[k];
    __syncthreads();

    // phase 3: warp-per-dst aggregation (coalesced V gathers)
    const float* Ve = V + (size_t)e * Ns * 32;
    for (int dd = wid; dd < 256; dd += 8) {
        int dg = e * 512 + tile * 256 + dd;
        float m = -3.4e38f;
#pragma unroll
        for (int k = 0; k < KNN; ++k) {
            int s = idxs[dd * KNN + k];
            m = fmaxf(m, Ve[s * 32 + lane]);
        }
        out[(size_t)dg * 32 + lane] = eluf(U[(size_t)dg * 32 + lane] + m);
    }
}

// ---------------- mean pool + head MLP + sigmoid -----------------------------
__global__ void pool_k(const float* __restrict__ f3,
                       const float* __restrict__ W1, const float* __restrict__ b1,
                       const float* __restrict__ W2, const float* __restrict__ b2,
                       float* __restrict__ out, int out_size)
{
    int e = blockIdx.x;
    int tid = threadIdx.x;
    int j = tid & 31, g = tid >> 5;
    const float* base = f3 + (size_t)e * 512 * 32;
    float acc = 0.f;
    for (int r = g; r < 512; r += 8) acc += base[r * 32 + j];
    __shared__ float red[8][32];
    red[g][j] = acc;
    __syncthreads();
    if (tid < 32) {
        float s = 0.f;
#pragma unroll
        for (int gg = 0; gg < 8; ++gg) s += red[gg][tid];
        float pooled = s * (1.f / 512.f);
        float h = b1[tid];
#pragma unroll
        for (int i = 0; i < 32; ++i)
            h = fmaf(__shfl_sync(0xffffffffu, pooled, i), W1[i * 32 + tid], h);
        h = eluf(h);
        float t = h * W2[tid];
#pragma unroll
        for (int o = 16; o; o >>= 1) t += __shfl_down_sync(0xffffffffu, t, o);
        if (tid == 0) {
            float prob = 1.f / (1.f + expf(-(t + b2[0])));
            out[e] = prob;
            if (out_size == 2 * BB) out[BB + e] = (float)e;                       // float concat
            else if (out_size == 3 * BB) ((long long*)(out + BB))[e] = (long long)e; // raw int64 tail
        }
    }
}

// ---------------- launch ------------------------------------------------------
extern "C" void kernel_launch(void* const* d_in, const int* in_sizes, int n_in,
                              void* d_out, int out_size)
{
    const float* x_sv   = (const float*)d_in[0];
    const float* x_trk  = (const float*)d_in[1];
    const float* x_pfc  = (const float*)d_in[2];
    // d_in[3..5] = batch indices (unused; layout is dense per event)
    const float* sv_W1  = (const float*)d_in[6];
    const float* sv_b1  = (const float*)d_in[7];
    const float* sv_W2  = (const float*)d_in[8];
    const float* sv_b2  = (const float*)d_in[9];
    const float* trk_W1 = (const float*)d_in[10];
    const float* trk_b1 = (const float*)d_in[11];
    const float* trk_W2 = (const float*)d_in[12];
    const float* trk_b2 = (const float*)d_in[13];
    const float* pfc_W1 = (const float*)d_in[14];
    const float* pfc_b1 = (const float*)d_in[15];
    const float* pfc_W2 = (const float*)d_in[16];
    const float* pfc_b2 = (const float*)d_in[17];
    const float* conv_W = (const float*)d_in[18];
    const float* conv_b = (const float*)d_in[19];
    const float* out_W1 = (const float*)d_in[20];
    const float* out_b1 = (const float*)d_in[21];
    const float* out_W2 = (const float*)d_in[22];
    const float* out_b2 = (const float*)d_in[23];
    float* out = (float*)d_out;

    float *sv, *trk, *pfc, *U, *V, *f1, *f2, *f3;
    cudaGetSymbolAddress((void**)&sv,  g_sv);
    cudaGetSymbolAddress((void**)&trk, g_trk);
    cudaGetSymbolAddress((void**)&pfc, g_pfc);
    cudaGetSymbolAddress((void**)&U,   g_U);
    cudaGetSymbolAddress((void**)&V,   g_V);
    cudaGetSymbolAddress((void**)&f1,  g_f1);
    cudaGetSymbolAddress((void**)&f2,  g_f2);
    cudaGetSymbolAddress((void**)&f3,  g_f3);

    // opt-in to large dynamic smem for the kNN kernel (idempotent, non-stream API)
    cudaFuncSetAttribute(knn_k, cudaFuncAttributeMaxDynamicSharedMemorySize, 80 * 1024);

    const int nSV  = BB * N_SV;
    const int nTRK = BB * N_TRK;
    const int nPFC = BB * N_PFC;

    // encoders
    encode_k<14><<<nSV  / 8, 256>>>(x_sv,  sv_W1,  sv_b1,  sv_W2,  sv_b2,  sv,  nSV);
    encode_k<30><<<nTRK / 8, 256>>>(x_trk, trk_W1, trk_b1, trk_W2, trk_b2, trk, nTRK);
    encode_k<10><<<nPFC / 8, 256>>>(x_pfc, pfc_W1, pfc_b1, pfc_W2, pfc_b2, pfc, nPFC);

    size_t smem64  = (size_t)(N_SV  * 32 + N_SV ) * 4 + 256 * KNN * 4;
    size_t smem512 = (size_t)(N_PFC * 32 + N_PFC) * 4 + 256 * KNN * 4;

    // conv1: sv -> trk
    lin32_k<<<nSV  / 8, 256>>>(sv,  conv_W, conv_b, V, nSV,  1);
    lin32_k<<<nTRK / 8, 256>>>(trk, conv_W, conv_b, U, nTRK, 0);
    knn_k<<<BB * 2, 256, smem64>>>(sv, trk, V, U, f1, N_SV);

    // conv2: pfc -> trk
    lin32_k<<<nPFC / 8, 256>>>(pfc, conv_W, conv_b, V, nPFC, 1);
    lin32_k<<<nTRK / 8, 256>>>(trk, conv_W, conv_b, U, nTRK, 0);
    knn_k<<<BB * 2, 256, smem512>>>(pfc, trk, V, U, f2, N_PFC);

    // conv3: f1 -> f2
    lin32_k<<<nTRK / 8, 256>>>(f1, conv_W, conv_b, V, nTRK, 1);
    lin32_k<<<nTRK / 8, 256>>>(f2, conv_W, conv_b, U, nTRK, 0);
    knn_k<<<BB * 2, 256, smem512>>>(f1, f2, V, U, f3, N_TRK);

    // pool + head
    pool_k<<<BB, 256>>>(f3, out_W1, out_b1, out_W2, out_b2, out, out_size);
}

// round 2
// speedup vs baseline: 1.0355x; 1.0355x over previous
#include <cuda_runtime.h>
#include <math.h>

#define BB 256
#define N_SV 64
#define N_TRK 512
#define N_PFC 512
#define KNN 8
#define HH 32
#define CAP 16   // per-thread candidate buffer slots

// ---------------- scratch (static device arrays; no allocation) -------------
__device__ float g_sv [BB * N_SV  * HH];
__device__ float g_trk[BB * N_TRK * HH];
__device__ float g_pfc[BB * N_PFC * HH];
__device__ float g_U  [BB * N_TRK * HH];
__device__ float g_V  [BB * N_PFC * HH];
__device__ float g_V1 [BB * N_SV  * HH];
__device__ float g_f1 [BB * N_TRK * HH];
__device__ float g_f2 [BB * N_TRK * HH];
__device__ float g_f3 [BB * N_TRK * HH];

__device__ __forceinline__ float eluf(float x) {
    return x > 0.f ? x : (expf(x) - 1.f);
}

// ---------------- encoder: 2-layer MLP, warp-per-node ----------------------
template <int FIN>
__global__ void encode_k(const float* __restrict__ x,
                         const float* __restrict__ W1, const float* __restrict__ b1,
                         const float* __restrict__ W2, const float* __restrict__ b2,
                         float* __restrict__ out, int n)
{
    __shared__ float w1s[FIN * 32];
    __shared__ float w2s[32 * 32];
    __shared__ float b1s[32], b2s[32];
    int tid = threadIdx.x;
    for (int i = tid; i < FIN * 32; i += 256) w1s[i] = W1[i];
    for (int i = tid; i < 1024;     i += 256) w2s[i] = W2[i];
    if (tid < 32) { b1s[tid] = b1[tid]; b2s[tid] = b2[tid]; }
    __syncthreads();

    int node = blockIdx.x * 8 + (tid >> 5);
    int lane = tid & 31;
    if (node >= n) return;

    float xv = (lane < FIN) ? x[node * FIN + lane] : 0.f;
    float h = b1s[lane];
#pragma unroll
    for (int i = 0; i < FIN; ++i)
        h = fmaf(__shfl_sync(0xffffffffu, xv, i), w1s[i * 32 + lane], h);
    h = eluf(h);

    float o = b2s[lane];
#pragma unroll
    for (int i = 0; i < 32; ++i)
        o = fmaf(__shfl_sync(0xffffffffu, h, i), w2s[i * 32 + lane], o);
    out[node * 32 + lane] = eluf(o);
}

// ---------------- 32x32 linear (mode 0: (Wa-Wb)+b, mode 1: Wb) -------------
// 4 independent nodes per warp to break the shfl latency chain.
__global__ void lin32_k(const float* __restrict__ in,
                        const float* __restrict__ convW, const float* __restrict__ convB,
                        float* __restrict__ out, int n, int mode)
{
    __shared__ float ws[1024];
    __shared__ float bs[32];
    int tid = threadIdx.x;
    for (int i = tid; i < 1024; i += 256)
        ws[i] = (mode == 0) ? (convW[i] - convW[1024 + i]) : convW[1024 + i];
    if (tid < 32) bs[tid] = (mode == 0) ? convB[tid] : 0.f;
    __syncthreads();

    int lane = tid & 31, wid = tid >> 5;
    int nb = blockIdx.x * 32 + wid * 4;
    if (nb >= n) return;

    float xv0 = in[(size_t)(nb + 0) * 32 + lane];
    float xv1 = in[(size_t)(nb + 1) * 32 + lane];
    float xv2 = in[(size_t)(nb + 2) * 32 + lane];
    float xv3 = in[(size_t)(nb + 3) * 32 + lane];
    float o0 = bs[lane], o1 = o0, o2 = o0, o3 = o0;
#pragma unroll
    for (int i = 0; i < 32; ++i) {
        float w = ws[i * 32 + lane];
        o0 = fmaf(__shfl_sync(0xffffffffu, xv0, i), w, o0);
        o1 = fmaf(__shfl_sync(0xffffffffu, xv1, i), w, o1);
        o2 = fmaf(__shfl_sync(0xffffffffu, xv2, i), w, o2);
        o3 = fmaf(__shfl_sync(0xffffffffu, xv3, i), w, o3);
    }
    out[(size_t)(nb + 0) * 32 + lane] = o0;
    out[(size_t)(nb + 1) * 32 + lane] = o1;
    out[(size_t)(nb + 2) * 32 + lane] = o2;
    out[(size_t)(nb + 3) * 32 + lane] = o3;
}

// ---------------- kNN + max aggregation -------------------------------------
// Scores via packed fma.rn.f32x2. Top-8 via threshold + branch-free candidate
// buffer in smem; flushes are warp-uniform and self-throttling.
__global__ void __launch_bounds__(256) knn_k(
                      const float* __restrict__ src_enc,
                      const float* __restrict__ dst_enc,
                      const float* __restrict__ V,
                      const float* __restrict__ U,
                      float* __restrict__ out, int Ns)
{
    extern __shared__ float sm[];
    float*  srcf = sm;                        // Ns*32 floats
    float*  sq   = sm + Ns * 32;              // Ns floats
    int*    idxs = (int*)(sq + Ns);           // 256*8 ints
    float2* buf  = (float2*)(idxs + 256 * KNN); // 256*CAP float2

    int tid  = threadIdx.x;
    int lane = tid & 31;
    int wid  = tid >> 5;
    int e    = blockIdx.x >> 1;
    int tile = blockIdx.x & 1;

    const float* sbase = src_enc + (size_t)e * Ns * 32;
    for (int i = tid; i < Ns * 32; i += 256) srcf[i] = sbase[i];
    __syncthreads();

    for (int r = wid; r < Ns; r += 8) {
        float v = srcf[r * 32 + lane];
        v *= v;
#pragma unroll
        for (int o = 16; o; o >>= 1) v += __shfl_down_sync(0xffffffffu, v, o);
        if (lane == 0) sq[r] = v;
    }
    __syncthreads();

    // ---- phase 2: streaming scores + threshold-buffered top-8 ----
    int dgn = e * 512 + tile * 256 + tid;

    unsigned long long xi[16];   // (-2*dst) packed as f32x2
    {
        const float4* drow = reinterpret_cast<const float4*>(dst_enc + (size_t)dgn * 32);
#pragma unroll
        for (int q = 0; q < 8; ++q) {
            float4 v = drow[q];
            float a = -2.f * v.x, b = -2.f * v.y, c = -2.f * v.z, d = -2.f * v.w;
            asm("mov.b64 %0, {%1, %2};" : "=l"(xi[2 * q + 0]) : "f"(a), "f"(b));
            asm("mov.b64 %0, {%1, %2};" : "=l"(xi[2 * q + 1]) : "f"(c), "f"(d));
        }
    }

    float dist[KNN];
    int   idx [KNN];
#pragma unroll
    for (int k = 0; k < KNN; ++k) { dist[k] = 3.4e38f; idx[k] = 0; }

    float T = 3.4e38f;
    int cnt = 0;
    unsigned src_sa = (unsigned)__cvta_generic_to_shared(srcf);
    unsigned buf_sa = (unsigned)__cvta_generic_to_shared(buf + tid * CAP);
    float2* mybuf = buf + tid * CAP;

    for (int s0 = 0; s0 < Ns; s0 += 4) {
        float scs[4];
#pragma unroll
        for (int j = 0; j < 4; ++j) {
            int s = s0 + j;
            unsigned addr = src_sa + (unsigned)s * 128u;
            unsigned long long acc0 = 0ull, acc1 = 0ull;
#pragma unroll
            for (int q = 0; q < 4; ++q) {
                unsigned long long p0, p1, p2, p3;
                asm("ld.shared.v2.b64 {%0,%1},[%2];"
                    : "=l"(p0), "=l"(p1) : "r"(addr + q * 32u));
                asm("ld.shared.v2.b64 {%0,%1},[%2];"
                    : "=l"(p2), "=l"(p3) : "r"(addr + q * 32u + 16u));
                asm("fma.rn.f32x2 %0, %1, %2, %0;" : "+l"(acc0) : "l"(xi[4 * q + 0]), "l"(p0));
                asm("fma.rn.f32x2 %0, %1, %2, %0;" : "+l"(acc1) : "l"(xi[4 * q + 1]), "l"(p1));
                asm("fma.rn.f32x2 %0, %1, %2, %0;" : "+l"(acc0) : "l"(xi[4 * q + 2]), "l"(p2));
                asm("fma.rn.f32x2 %0, %1, %2, %0;" : "+l"(acc1) : "l"(xi[4 * q + 3]), "l"(p3));
            }
            float l0, h0, l1, h1;
            asm("mov.b64 {%0,%1}, %2;" : "=f"(l0), "=f"(h0) : "l"(acc0));
            asm("mov.b64 {%0,%1}, %2;" : "=f"(l1), "=f"(h1) : "l"(acc1));
            scs[j] = sq[s] + ((l0 + h0) + (l1 + h1));
        }
        // branch-free predicated appends
#pragma unroll
        for (int j = 0; j < 4; ++j) {
            float fidx = __int_as_float(s0 + j);
            asm volatile(
                "{.reg .pred p; setp.lt.f32 p, %1, %2; @p st.shared.v2.f32 [%0], {%1, %3};}"
                :: "r"(buf_sa + (unsigned)cnt * 8u), "f"(scs[j]), "f"(T), "f"(fidx)
                : "memory");
            cnt += (scs[j] < T) ? 1 : 0;
        }
        // warp-uniform flush check
        if (__any_sync(0xffffffffu, cnt >= CAP - 4)) {
            for (int i = 0; i < cnt; ++i) {
                float2 c = mybuf[i];
                float v = c.x;
                if (v < dist[KNN - 1]) {
                    dist[KNN - 1] = v; idx[KNN - 1] = __float_as_int(c.y);
#pragma unroll
                    for (int p = KNN - 1; p > 0; --p) {
                        if (dist[p] < dist[p - 1]) {
                            float td = dist[p]; dist[p] = dist[p - 1]; dist[p - 1] = td;
                            int   ti = idx[p];  idx[p]  = idx[p - 1];  idx[p - 1]  = ti;
                        }
                    }
                }
            }
            cnt = 0;
            T = dist[KNN - 1];
        }
    }
    // final flush
    for (int i = 0; i < cnt; ++i) {
        float2 c = mybuf[i];
        float v = c.x;
        if (v < dist[KNN - 1]) {
            dist[KNN - 1] = v; idx[KNN - 1] = __float_as_int(c.y);
#pragma unroll
            for (int p = KNN - 1; p > 0; --p) {
                if (dist[p] < dist[p - 1]) {
                    float td = dist[p]; dist[p] = dist[p - 1]; dist[p - 1] = td;
                    int   ti = idx[p];  idx[p]  = idx[p - 1];  idx[p - 1]  = ti;
                }
            }
        }
    }

#pragma unroll
    for (int k = 0; k < KNN; ++k) idxs[tid * KNN + k] = idx[k];
    __syncthreads();

    // ---- phase 3: warp-per-dst aggregation (coalesced V gathers) ----
    const float* Ve = V + (size_t)e * Ns * 32;
    for (int dd = wid; dd < 256; dd += 8) {
        int dg = e * 512 + tile * 256 + dd;
        float m = -3.4e38f;
#pragma unroll
        for (int k = 0; k < KNN; ++k) {
            int s = idxs[dd * KNN + k];
            m = fmaxf(m, Ve[s * 32 + lane]);
        }
        out[(size_t)dg * 32 + lane] = eluf(U[(size_t)dg * 32 + lane] + m);
    }
}

// ---------------- mean pool + head MLP + sigmoid -----------------------------
__global__ void pool_k(const float* __restrict__ f3,
                       const float* __restrict__ W1, const float* __restrict__ b1,
                       const float* __restrict__ W2, const float* __restrict__ b2,
                       float* __restrict__ out, int out_size)
{
    int e = blockIdx.x;
    int tid = threadIdx.x;
    int j = tid & 31, g = tid >> 5;
    const float* base = f3 + (size_t)e * 512 * 32;
    float acc = 0.f;
    for (int r = g; r < 512; r += 8) acc += base[r * 32 + j];
    __shared__ float red[8][32];
    red[g][j] = acc;
    __syncthreads();
    if (tid < 32) {
        float s = 0.f;
#pragma unroll
        for (int gg = 0; gg < 8; ++gg) s += red[gg][tid];
        float pooled = s * (1.f / 512.f);
        float h = b1[tid];
#pragma unroll
        for (int i = 0; i < 32; ++i)
            h = fmaf(__shfl_sync(0xffffffffu, pooled, i), W1[i * 32 + tid], h);
        h = eluf(h);
        float t = h * W2[tid];
#pragma unroll
        for (int o = 16; o; o >>= 1) t += __shfl_down_sync(0xffffffffu, t, o);
        if (tid == 0) {
            float prob = 1.f / (1.f + expf(-(t + b2[0])));
            out[e] = prob;
            if (out_size == 2 * BB) out[BB + e] = (float)e;
            else if (out_size == 3 * BB) ((long long*)(out + BB))[e] = (long long)e;
        }
    }
}

// ---------------- launch ------------------------------------------------------
extern "C" void kernel_launch(void* const* d_in, const int* in_sizes, int n_in,
                              void* d_out, int out_size)
{
    const float* x_sv   = (const float*)d_in[0];
    const float* x_trk  = (const float*)d_in[1];
    const float* x_pfc  = (const float*)d_in[2];
    const float* sv_W1  = (const float*)d_in[6];
    const float* sv_b1  = (const float*)d_in[7];
    const float* sv_W2  = (const float*)d_in[8];
    const float* sv_b2  = (const float*)d_in[9];
    const float* trk_W1 = (const float*)d_in[10];
    const float* trk_b1 = (const float*)d_in[11];
    const float* trk_W2 = (const float*)d_in[12];
    const float* trk_b2 = (const float*)d_in[13];
    const float* pfc_W1 = (const float*)d_in[14];
    const float* pfc_b1 = (const float*)d_in[15];
    const float* pfc_W2 = (const float*)d_in[16];
    const float* pfc_b2 = (const float*)d_in[17];
    const float* conv_W = (const float*)d_in[18];
    const float* conv_b = (const float*)d_in[19];
    const float* out_W1 = (const float*)d_in[20];
    const float* out_b1 = (const float*)d_in[21];
    const float* out_W2 = (const float*)d_in[22];
    const float* out_b2 = (const float*)d_in[23];
    float* out = (float*)d_out;

    float *sv, *trk, *pfc, *U, *V, *V1, *f1, *f2, *f3;
    cudaGetSymbolAddress((void**)&sv,  g_sv);
    cudaGetSymbolAddress((void**)&trk, g_trk);
    cudaGetSymbolAddress((void**)&pfc, g_pfc);
    cudaGetSymbolAddress((void**)&U,   g_U);
    cudaGetSymbolAddress((void**)&V,   g_V);
    cudaGetSymbolAddress((void**)&V1,  g_V1);
    cudaGetSymbolAddress((void**)&f1,  g_f1);
    cudaGetSymbolAddress((void**)&f2,  g_f2);
    cudaGetSymbolAddress((void**)&f3,  g_f3);

    cudaFuncSetAttribute(knn_k, cudaFuncAttributeMaxDynamicSharedMemorySize, 116 * 1024);

    const int nSV  = BB * N_SV;
    const int nTRK = BB * N_TRK;
    const int nPFC = BB * N_PFC;

    encode_k<14><<<nSV  / 8, 256>>>(x_sv,  sv_W1,  sv_b1,  sv_W2,  sv_b2,  sv,  nSV);
    encode_k<30><<<nTRK / 8, 256>>>(x_trk, trk_W1, trk_b1, trk_W2, trk_b2, trk, nTRK);
    encode_k<10><<<nPFC / 8, 256>>>(x_pfc, pfc_W1, pfc_b1, pfc_W2, pfc_b2, pfc, nPFC);

    size_t smem64  = (size_t)(N_SV  * 32 + N_SV ) * 4 + 256 * KNN * 4 + 256 * CAP * 8;
    size_t smem512 = (size_t)(N_PFC * 32 + N_PFC) * 4 + 256 * KNN * 4 + 256 * CAP * 8;

    // shared pre-linears
    lin32_k<<<nSV  / 32, 256>>>(sv,  conv_W, conv_b, V1, nSV,  1);
    lin32_k<<<nTRK / 32, 256>>>(trk, conv_W, conv_b, U,  nTRK, 0);  // U(trk): conv1 + conv2
    lin32_k<<<nPFC / 32, 256>>>(pfc, conv_W, conv_b, V,  nPFC, 1);

    knn_k<<<BB * 2, 256, smem64 >>>(sv,  trk, V1, U, f1, N_SV);
    knn_k<<<BB * 2, 256, smem512>>>(pfc, trk, V,  U, f2, N_PFC);

    // conv3: f1 -> f2
    lin32_k<<<nTRK / 32, 256>>>(f1, conv_W, conv_b, V, nTRK, 1);
    lin32_k<<<nTRK / 32, 256>>>(f2, conv_W, conv_b, U, nTRK, 0);
    knn_k<<<BB * 2, 256, smem512>>>(f1, f2, V, U, f3, N_TRK);

    pool_k<<<BB, 256>>>(f3, out_W1, out_b1, out_W2, out_b2, out, out_size);
}

// round 3
// speedup vs baseline: 1.3594x; 1.3127x over previous
#include <cuda_runtime.h>
#include <math.h>

#define BB 256
#define N_SV 64
#define N_TRK 512
#define N_PFC 512
#define KNN 8
#define HH 32
#define CAP 6    // per-dst candidate buffer slots

// ---------------- scratch (static device arrays; no allocation) -------------
__device__ float g_sv [BB * N_SV  * HH];
__device__ float g_trk[BB * N_TRK * HH];
__device__ float g_pfc[BB * N_PFC * HH];
__device__ float g_U  [BB * N_TRK * HH];
__device__ float g_V  [BB * N_PFC * HH];
__device__ float g_V1 [BB * N_SV  * HH];
__device__ float g_f1 [BB * N_TRK * HH];
__device__ float g_f2 [BB * N_TRK * HH];
__device__ float g_f3 [BB * N_TRK * HH];

__device__ __forceinline__ float eluf(float x) {
    return x > 0.f ? x : (expf(x) - 1.f);
}

// ================= fused encoder: 2-layer MLP, 4 nodes per warp =============
template <int FIN>
__device__ __forceinline__ void encode_body(
    const float* __restrict__ x,
    const float* __restrict__ W1, const float* __restrict__ b1,
    const float* __restrict__ W2, const float* __restrict__ b2,
    float* __restrict__ out, int blk,
    float* w1s, float* w2s, float* b1s, float* b2s)
{
    int tid = threadIdx.x;
    for (int i = tid; i < FIN * 32; i += 256) w1s[i] = W1[i];
    for (int i = tid; i < 1024;     i += 256) w2s[i] = W2[i];
    if (tid < 32) { b1s[tid] = b1[tid]; b2s[tid] = b2[tid]; }
    __syncthreads();

    int lane = tid & 31, wid = tid >> 5;
    int nb = blk * 32 + wid * 4;

    float xv0 = (lane < FIN) ? x[(size_t)(nb + 0) * FIN + lane] : 0.f;
    float xv1 = (lane < FIN) ? x[(size_t)(nb + 1) * FIN + lane] : 0.f;
    float xv2 = (lane < FIN) ? x[(size_t)(nb + 2) * FIN + lane] : 0.f;
    float xv3 = (lane < FIN) ? x[(size_t)(nb + 3) * FIN + lane] : 0.f;

    float h0 = b1s[lane], h1 = h0, h2 = h0, h3 = h0;
#pragma unroll
    for (int i = 0; i < FIN; ++i) {
        float w = w1s[i * 32 + lane];
        h0 = fmaf(__shfl_sync(0xffffffffu, xv0, i), w, h0);
        h1 = fmaf(__shfl_sync(0xffffffffu, xv1, i), w, h1);
        h2 = fmaf(__shfl_sync(0xffffffffu, xv2, i), w, h2);
        h3 = fmaf(__shfl_sync(0xffffffffu, xv3, i), w, h3);
    }
    h0 = eluf(h0); h1 = eluf(h1); h2 = eluf(h2); h3 = eluf(h3);

    float o0 = b2s[lane], o1 = o0, o2 = o0, o3 = o0;
#pragma unroll
    for (int i = 0; i < 32; ++i) {
        float w = w2s[i * 32 + lane];
        o0 = fmaf(__shfl_sync(0xffffffffu, h0, i), w, o0);
        o1 = fmaf(__shfl_sync(0xffffffffu, h1, i), w, o1);
        o2 = fmaf(__shfl_sync(0xffffffffu, h2, i), w, o2);
        o3 = fmaf(__shfl_sync(0xffffffffu, h3, i), w, o3);
    }
    out[(size_t)(nb + 0) * 32 + lane] = eluf(o0);
    out[(size_t)(nb + 1) * 32 + lane] = eluf(o1);
    out[(size_t)(nb + 2) * 32 + lane] = eluf(o2);
    out[(size_t)(nb + 3) * 32 + lane] = eluf(o3);
}

// grid = 512 (sv) + 4096 (trk) + 4096 (pfc) = 8704 blocks, 32 nodes/block
__global__ void __launch_bounds__(256) encode_all_k(
    const float* x_sv, const float* x_trk, const float* x_pfc,
    const float* svW1, const float* svb1, const float* svW2, const float* svb2,
    const float* tkW1, const float* tkb1, const float* tkW2, const float* tkb2,
    const float* pfW1, const float* pfb1, const float* pfW2, const float* pfb2,
    float* o_sv, float* o_trk, float* o_pfc)
{
    __shared__ float w1s[32 * 32];
    __shared__ float w2s[32 * 32];
    __shared__ float b1s[32], b2s[32];
    int b = blockIdx.x;
    if (b < 512)
        encode_body<14>(x_sv, svW1, svb1, svW2, svb2, o_sv, b, w1s, w2s, b1s, b2s);
    else if (b < 4608)
        encode_body<30>(x_trk, tkW1, tkb1, tkW2, tkb2, o_trk, b - 512, w1s, w2s, b1s, b2s);
    else
        encode_body<10>(x_pfc, pfW1, pfb1, pfW2, pfb2, o_pfc, b - 4608, w1s, w2s, b1s, b2s);
}

// ================ fused 32x32 linear (mode 0: (Wa-Wb)+b, mode 1: Wb) ========
__device__ __forceinline__ void lin_body(
    const float* __restrict__ in, float* __restrict__ out, int blk, int mode,
    const float* __restrict__ convW, const float* __restrict__ convB,
    float* ws, float* bs)
{
    int tid = threadIdx.x;
    for (int i = tid; i < 1024; i += 256)
        ws[i] = (mode == 0) ? (convW[i] - convW[1024 + i]) : convW[1024 + i];
    if (tid < 32) bs[tid] = (mode == 0) ? convB[tid] : 0.f;
    __syncthreads();

    int lane = tid & 31, wid = tid >> 5;
    int nb = blk * 32 + wid * 4;

    float xv0 = in[(size_t)(nb + 0) * 32 + lane];
    float xv1 = in[(size_t)(nb + 1) * 32 + lane];
    float xv2 = in[(size_t)(nb + 2) * 32 + lane];
    float xv3 = in[(size_t)(nb + 3) * 32 + lane];
    float o0 = bs[lane], o1 = o0, o2 = o0, o3 = o0;
#pragma unroll
    for (int i = 0; i < 32; ++i) {
        float w = ws[i * 32 + lane];
        o0 = fmaf(__shfl_sync(0xffffffffu, xv0, i), w, o0);
        o1 = fmaf(__shfl_sync(0xffffffffu, xv1, i), w, o1);
        o2 = fmaf(__shfl_sync(0xffffffffu, xv2, i), w, o2);
        o3 = fmaf(__shfl_sync(0xffffffffu, xv3, i), w, o3);
    }
    out[(size_t)(nb + 0) * 32 + lane] = o0;
    out[(size_t)(nb + 1) * 32 + lane] = o1;
    out[(size_t)(nb + 2) * 32 + lane] = o2;
    out[(size_t)(nb + 3) * 32 + lane] = o3;
}

// grid 8704: sv->V1 (mode1), trk->U (mode0), pfc->V (mode1)
__global__ void __launch_bounds__(256) lin_all_k(
    const float* sv, const float* trk, const float* pfc,
    float* V1, float* U, float* V,
    const float* convW, const float* convB)
{
    __shared__ float ws[1024];
    __shared__ float bs[32];
    int b = blockIdx.x;
    if (b < 512)        lin_body(sv,  V1, b,        1, convW, convB, ws, bs);
    else if (b < 4608)  lin_body(trk, U,  b - 512,  0, convW, convB, ws, bs);
    else                lin_body(pfc, V,  b - 4608, 1, convW, convB, ws, bs);
}

// grid 8192: f1->V (mode1), f2->U (mode0)
__global__ void __launch_bounds__(256) lin2_k(
    const float* f1, const float* f2, float* V, float* U,
    const float* convW, const float* convB)
{
    __shared__ float ws[1024];
    __shared__ float bs[32];
    int b = blockIdx.x;
    if (b < 4096) lin_body(f1, V, b,        1, convW, convB, ws, bs);
    else          lin_body(f2, U, b - 4096, 0, convW, convB, ws, bs);
}

// ================= kNN + max aggregation ====================================
// One block per event; 256 threads; each thread owns 2 dsts (tid, tid+256).
// Broadcast LDS of src rows is shared across both score accumulations.
__device__ __forceinline__ void flush_buf(const float2* mybuf, int& cnt,
                                          float (&dist)[KNN], int (&idx)[KNN])
{
    for (int i = 0; i < cnt; ++i) {
        float2 c = mybuf[i];
        if (c.x < dist[KNN - 1]) {
            dist[KNN - 1] = c.x; idx[KNN - 1] = __float_as_int(c.y);
#pragma unroll
            for (int p = KNN - 1; p > 0; --p) {
                if (dist[p] < dist[p - 1]) {
                    float td = dist[p]; dist[p] = dist[p - 1]; dist[p - 1] = td;
                    int   ti = idx[p];  idx[p]  = idx[p - 1];  idx[p - 1]  = ti;
                }
            }
        }
    }
    cnt = 0;
}

__global__ void __launch_bounds__(256, 2) knn_k(
                      const float* __restrict__ src_enc,
                      const float* __restrict__ dst_enc,
                      const float* __restrict__ V,
                      const float* __restrict__ U,
                      float* __restrict__ out, int Ns)
{
    extern __shared__ float sm[];
    float*  srcf = sm;                           // Ns*32
    float*  sq   = sm + Ns * 32;                 // Ns
    int*    idxs = (int*)(sq + Ns);              // 512*8
    float2* buf  = (float2*)(idxs + 512 * KNN);  // 256*2*CAP

    int tid  = threadIdx.x;
    int lane = tid & 31;
    int wid  = tid >> 5;
    int e    = blockIdx.x;

    {   // stage src features (float4)
        const float4* sb4 = reinterpret_cast<const float4*>(src_enc + (size_t)e * Ns * 32);
        float4* sf4 = reinterpret_cast<float4*>(srcf);
        for (int i = tid; i < Ns * 8; i += 256) sf4[i] = sb4[i];
    }
    __syncthreads();

    for (int r = wid; r < Ns; r += 8) {
        float v = srcf[r * 32 + lane];
        v *= v;
#pragma unroll
        for (int o = 16; o; o >>= 1) v += __shfl_down_sync(0xffffffffu, v, o);
        if (lane == 0) sq[r] = v;
    }
    __syncthreads();

    // ---- load both dst rows, packed as f32x2 of (-2*dst) ----
    unsigned long long xi0[16], xi1[16];
    {
        const float4* d0 = reinterpret_cast<const float4*>(dst_enc + ((size_t)e * 512 + tid) * 32);
        const float4* d1 = reinterpret_cast<const float4*>(dst_enc + ((size_t)e * 512 + tid + 256) * 32);
#pragma unroll
        for (int q = 0; q < 8; ++q) {
            float4 v = d0[q];
            float a = -2.f * v.x, b = -2.f * v.y, c = -2.f * v.z, d = -2.f * v.w;
            asm("mov.b64 %0, {%1, %2};" : "=l"(xi0[2 * q + 0]) : "f"(a), "f"(b));
            asm("mov.b64 %0, {%1, %2};" : "=l"(xi0[2 * q + 1]) : "f"(c), "f"(d));
            v = d1[q];
            a = -2.f * v.x; b = -2.f * v.y; c = -2.f * v.z; d = -2.f * v.w;
            asm("mov.b64 %0, {%1, %2};" : "=l"(xi1[2 * q + 0]) : "f"(a), "f"(b));
            asm("mov.b64 %0, {%1, %2};" : "=l"(xi1[2 * q + 1]) : "f"(c), "f"(d));
        }
    }

    float dist0[KNN], dist1[KNN];
    int   idx0 [KNN], idx1 [KNN];
#pragma unroll
    for (int k = 0; k < KNN; ++k) {
        dist0[k] = 3.4e38f; idx0[k] = 0;
        dist1[k] = 3.4e38f; idx1[k] = 0;
    }

    float T0 = 3.4e38f, T1 = 3.4e38f;
    int cnt0 = 0, cnt1 = 0;
    unsigned src_sa  = (unsigned)__cvta_generic_to_shared(srcf);
    float2* mybuf0 = buf + tid * 2 * CAP;
    float2* mybuf1 = mybuf0 + CAP;
    unsigned buf0_sa = (unsigned)__cvta_generic_to_shared(mybuf0);
    unsigned buf1_sa = (unsigned)__cvta_generic_to_shared(mybuf1);

    for (int s0 = 0; s0 < Ns; s0 += 4) {
        float sc0[4], sc1[4];
#pragma unroll
        for (int j = 0; j < 4; ++j) {
            int s = s0 + j;
            unsigned addr = src_sa + (unsigned)s * 128u;
            unsigned long long a00 = 0ull, a01 = 0ull, a10 = 0ull, a11 = 0ull;
#pragma unroll
            for (int q = 0; q < 4; ++q) {
                unsigned long long p0, p1, p2, p3;
                asm("ld.shared.v2.b64 {%0,%1},[%2];"
                    : "=l"(p0), "=l"(p1) : "r"(addr + q * 32u));
                asm("ld.shared.v2.b64 {%0,%1},[%2];"
                    : "=l"(p2), "=l"(p3) : "r"(addr + q * 32u + 16u));
                asm("fma.rn.f32x2 %0, %1, %2, %0;" : "+l"(a00) : "l"(xi0[4 * q + 0]), "l"(p0));
                asm("fma.rn.f32x2 %0, %1, %2, %0;" : "+l"(a10) : "l"(xi1[4 * q + 0]), "l"(p0));
                asm("fma.rn.f32x2 %0, %1, %2, %0;" : "+l"(a01) : "l"(xi0[4 * q + 1]), "l"(p1));
                asm("fma.rn.f32x2 %0, %1, %2, %0;" : "+l"(a11) : "l"(xi1[4 * q + 1]), "l"(p1));
                asm("fma.rn.f32x2 %0, %1, %2, %0;" : "+l"(a00) : "l"(xi0[4 * q + 2]), "l"(p2));
                asm("fma.rn.f32x2 %0, %1, %2, %0;" : "+l"(a10) : "l"(xi1[4 * q + 2]), "l"(p2));
                asm("fma.rn.f32x2 %0, %1, %2, %0;" : "+l"(a01) : "l"(xi0[4 * q + 3]), "l"(p3));
                asm("fma.rn.f32x2 %0, %1, %2, %0;" : "+l"(a11) : "l"(xi1[4 * q + 3]), "l"(p3));
            }
            float l0, h0, l1, h1, sqs = sq[s];
            asm("mov.b64 {%0,%1}, %2;" : "=f"(l0), "=f"(h0) : "l"(a00));
            asm("mov.b64 {%0,%1}, %2;" : "=f"(l1), "=f"(h1) : "l"(a01));
            sc0[j] = sqs + ((l0 + h0) + (l1 + h1));
            asm("mov.b64 {%0,%1}, %2;" : "=f"(l0), "=f"(h0) : "l"(a10));
            asm("mov.b64 {%0,%1}, %2;" : "=f"(l1), "=f"(h1) : "l"(a11));
            sc1[j] = sqs + ((l0 + h0) + (l1 + h1));
        }
#pragma unroll
        for (int j = 0; j < 4; ++j) {
            float fidx = __int_as_float(s0 + j);
            asm volatile(
                "{.reg .pred p; setp.lt.f32 p, %1, %2; @p st.shared.v2.f32 [%0], {%1, %3};}"
                :: "r"(buf0_sa + (unsigned)cnt0 * 8u), "f"(sc0[j]), "f"(T0), "f"(fidx)
                : "memory");
            cnt0 += (sc0[j] < T0) ? 1 : 0;
            asm volatile(
                "{.reg .pred p; setp.lt.f32 p, %1, %2; @p st.shared.v2.f32 [%0], {%1, %3};}"
                :: "r"(buf1_sa + (unsigned)cnt1 * 8u), "f"(sc1[j]), "f"(T1), "f"(fidx)
                : "memory");
            cnt1 += (sc1[j] < T1) ? 1 : 0;
        }
        int mc = (cnt0 > cnt1) ? cnt0 : cnt1;
        if (__any_sync(0xffffffffu, mc >= 3)) {
            flush_buf(mybuf0, cnt0, dist0, idx0);  T0 = dist0[KNN - 1];
            flush_buf(mybuf1, cnt1, dist1, idx1);  T1 = dist1[KNN - 1];
        }
    }
    flush_buf(mybuf0, cnt0, dist0, idx0);
    flush_buf(mybuf1, cnt1, dist1, idx1);

#pragma unroll
    for (int k = 0; k < KNN; ++k) {
        idxs[tid * KNN + k]         = idx0[k];
        idxs[(tid + 256) * KNN + k] = idx1[k];
    }
    __syncthreads();

    // ---- phase 3: warp-per-dst aggregation (coalesced V gathers) ----
    const float* Ve = V + (size_t)e * Ns * 32;
    for (int dd = wid; dd < 512; dd += 8) {
        int dg = e * 512 + dd;
        float m = -3.4e38f;
#pragma unroll
        for (int k = 0; k < KNN; ++k) {
            int s = idxs[dd * KNN + k];
            m = fmaxf(m, Ve[s * 32 + lane]);
        }
        out[(size_t)dg * 32 + lane] = eluf(U[(size_t)dg * 32 + lane] + m);
    }
}

// ---------------- mean pool + head MLP + sigmoid -----------------------------
__global__ void pool_k(const float* __restrict__ f3,
                       const float* __restrict__ W1, const float* __restrict__ b1,
                       const float* __restrict__ W2, const float* __restrict__ b2,
                       float* __restrict__ out, int out_size)
{
    int e = blockIdx.x;
    int tid = threadIdx.x;
    int j = tid & 31, g = tid >> 5;
    const float* base = f3 + (size_t)e * 512 * 32;
    float acc = 0.f;
    for (int r = g; r < 512; r += 8) acc += base[r * 32 + j];
    __shared__ float red[8][32];
    red[g][j] = acc;
    __syncthreads();
    if (tid < 32) {
        float s = 0.f;
#pragma unroll
        for (int gg = 0; gg < 8; ++gg) s += red[gg][tid];
        float pooled = s * (1.f / 512.f);
        float h = b1[tid];
#pragma unroll
        for (int i = 0; i < 32; ++i)
            h = fmaf(__shfl_sync(0xffffffffu, pooled, i), W1[i * 32 + tid], h);
        h = eluf(h);
        float t = h * W2[tid];
#pragma unroll
        for (int o = 16; o; o >>= 1) t += __shfl_down_sync(0xffffffffu, t, o);
        if (tid == 0) {
            float prob = 1.f / (1.f + expf(-(t + b2[0])));
            out[e] = prob;
            if (out_size == 2 * BB) out[BB + e] = (float)e;
            else if (out_size == 3 * BB) ((long long*)(out + BB))[e] = (long long)e;
        }
    }
}

// ---------------- launch ------------------------------------------------------
extern "C" void kernel_launch(void* const* d_in, const int* in_sizes, int n_in,
                              void* d_out, int out_size)
{
    const float* x_sv   = (const float*)d_in[0];
    const float* x_trk  = (const float*)d_in[1];
    const float* x_pfc  = (const float*)d_in[2];
    const float* sv_W1  = (const float*)d_in[6];
    const float* sv_b1  = (const float*)d_in[7];
    const float* sv_W2  = (const float*)d_in[8];
    const float* sv_b2  = (const float*)d_in[9];
    const float* trk_W1 = (const float*)d_in[10];
    const float* trk_b1 = (const float*)d_in[11];
    const float* trk_W2 = (const float*)d_in[12];
    const float* trk_b2 = (const float*)d_in[13];
    const float* pfc_W1 = (const float*)d_in[14];
    const float* pfc_b1 = (const float*)d_in[15];
    const float* pfc_W2 = (const float*)d_in[16];
    const float* pfc_b2 = (const float*)d_in[17];
    const float* conv_W = (const float*)d_in[18];
    const float* conv_b = (const float*)d_in[19];
    const float* out_W1 = (const float*)d_in[20];
    const float* out_b1 = (const float*)d_in[21];
    const float* out_W2 = (const float*)d_in[22];
    const float* out_b2 = (const float*)d_in[23];
    float* out = (float*)d_out;

    float *sv, *trk, *pfc, *U, *V, *V1, *f1, *f2, *f3;
    cudaGetSymbolAddress((void**)&sv,  g_sv);
    cudaGetSymbolAddress((void**)&trk, g_trk);
    cudaGetSymbolAddress((void**)&pfc, g_pfc);
    cudaGetSymbolAddress((void**)&U,   g_U);
    cudaGetSymbolAddress((void**)&V,   g_V);
    cudaGetSymbolAddress((void**)&V1,  g_V1);
    cudaGetSymbolAddress((void**)&f1,  g_f1);
    cudaGetSymbolAddress((void**)&f2,  g_f2);
    cudaGetSymbolAddress((void**)&f3,  g_f3);

    cudaFuncSetAttribute(knn_k, cudaFuncAttributeMaxDynamicSharedMemorySize, 112 * 1024);

    size_t smem64  = (size_t)N_SV  * 132 + 512 * KNN * 4 + 256 * 2 * CAP * 8;
    size_t smem512 = (size_t)N_PFC * 132 + 512 * KNN * 4 + 256 * 2 * CAP * 8;

    // 1: fused encoders
    encode_all_k<<<8704, 256>>>(x_sv, x_trk, x_pfc,
                                sv_W1, sv_b1, sv_W2, sv_b2,
                                trk_W1, trk_b1, trk_W2, trk_b2,
                                pfc_W1, pfc_b1, pfc_W2, pfc_b2,
                                sv, trk, pfc);
    // 2: fused pre-linears (V1, U, V)
    lin_all_k<<<8704, 256>>>(sv, trk, pfc, V1, U, V, conv_W, conv_b);
    // 3: conv1 sv->trk
    knn_k<<<BB, 256, smem64 >>>(sv,  trk, V1, U, f1, N_SV);
    // 4: conv2 pfc->trk
    knn_k<<<BB, 256, smem512>>>(pfc, trk, V,  U, f2, N_PFC);
    // 5: fused lin for conv3 (V<-f1, U<-f2)
    lin2_k<<<8192, 256>>>(f1, f2, V, U, conv_W, conv_b);
    // 6: conv3 f1->f2   (this is the launch ncu profiles with -s 5 -c 1)
    knn_k<<<BB, 256, smem512>>>(f1, f2, V, U, f3, N_TRK);
    // 7: pool + head
    pool_k<<<BB, 256>>>(f3, out_W1, out_b1, out_W2, out_b2, out, out_size);
}